// round 15
// baseline (speedup 1.0000x reference)
#include <cuda_runtime.h>
#include <cuda_bf16.h>
#include <math_constants.h>

// Problem constants
#define BB   4
#define TT   2048
#define CC   1024
#define HH   16
#define DD   64
#define GM   (BB*TT)      // 8192
#define GK   CC           // 1024
#define GN   (3*CC)       // 3072

// ---------------------------------------------------------------------------
// Device scratch (no allocs allowed)
// ---------------------------------------------------------------------------
__device__ __align__(128) __nv_bfloat16 g_a_hi[(size_t)GM * GK];
__device__ __align__(128) __nv_bfloat16 g_a_lo[(size_t)GM * GK];
__device__ __align__(128) __nv_bfloat16 g_wt_hi[(size_t)GN * GK];       // W^T
__device__ __align__(128) __nv_bfloat16 g_wt_lo[(size_t)GN * GK];
// QKV results as bf16 hi/lo per section
__device__ __align__(128) __nv_bfloat16 g_kh[(size_t)GM * CC];
__device__ __align__(128) __nv_bfloat16 g_kl[(size_t)GM * CC];
__device__ __align__(128) __nv_bfloat16 g_qh[(size_t)GM * CC];          // pre-scaled
__device__ __align__(128) __nv_bfloat16 g_ql[(size_t)GM * CC];
__device__ __align__(128) __nv_bfloat16 g_vh[(size_t)GM * CC];
__device__ __align__(128) __nv_bfloat16 g_vl[(size_t)GM * CC];

// Q pre-scale: (1/sqrt(64)) * log2(e)  -> softmax computed base-2
#define QSCALE 0.18033688011112042f

// ---------------------------------------------------------------------------
// Portable PTX helpers (sm_80+)
// ---------------------------------------------------------------------------
__device__ __forceinline__ unsigned smem_u32(const void* p) {
    unsigned a;
    asm("{ .reg .u64 t; cvta.to.shared.u64 t, %1; cvt.u32.u64 %0, t; }"
        : "=r"(a) : "l"(p));
    return a;
}
__device__ __forceinline__ void cp_async16(unsigned dst, const void* src) {
    asm volatile("cp.async.cg.shared.global [%0], [%1], 16;"
                 :: "r"(dst), "l"(src) : "memory");
}
__device__ __forceinline__ void cp_commit() {
    asm volatile("cp.async.commit_group;" ::: "memory");
}
template <int N>
__device__ __forceinline__ void cp_wait() {
    asm volatile("cp.async.wait_group %0;" :: "n"(N) : "memory");
}
__device__ __forceinline__ void ldmx4(unsigned& r0, unsigned& r1, unsigned& r2,
                                      unsigned& r3, unsigned addr) {
    asm volatile("ldmatrix.sync.aligned.m8n8.x4.shared.b16 {%0,%1,%2,%3}, [%4];"
                 : "=r"(r0), "=r"(r1), "=r"(r2), "=r"(r3) : "r"(addr));
}
__device__ __forceinline__ void ldmx4t(unsigned& r0, unsigned& r1, unsigned& r2,
                                       unsigned& r3, unsigned addr) {
    asm volatile("ldmatrix.sync.aligned.m8n8.x4.trans.shared.b16 {%0,%1,%2,%3}, [%4];"
                 : "=r"(r0), "=r"(r1), "=r"(r2), "=r"(r3) : "r"(addr));
}
__device__ __forceinline__ void mma_bf16(float* c, unsigned a0, unsigned a1,
                                         unsigned a2, unsigned a3,
                                         unsigned b0, unsigned b1) {
    asm volatile(
        "mma.sync.aligned.m16n8k16.row.col.f32.bf16.bf16.f32 "
        "{%0,%1,%2,%3}, {%4,%5,%6,%7}, {%8,%9}, {%0,%1,%2,%3};"
        : "+f"(c[0]), "+f"(c[1]), "+f"(c[2]), "+f"(c[3])
        : "r"(a0), "r"(a1), "r"(a2), "r"(a3), "r"(b0), "r"(b1));
}
// round-nearest split (used in GEMM epilogue)
__device__ __forceinline__ void split2(float x0, float x1, unsigned& hi, unsigned& lo) {
    __nv_bfloat16 h0 = __float2bfloat16(x0), h1 = __float2bfloat16(x1);
    float r0 = x0 - __bfloat162float(h0), r1 = x1 - __bfloat162float(h1);
    __nv_bfloat162 hv; hv.x = h0; hv.y = h1;
    __nv_bfloat162 lv; lv.x = __float2bfloat16(r0); lv.y = __float2bfloat16(r1);
    hi = *(unsigned*)&hv; lo = *(unsigned*)&lv;
}
// truncation split: hi = top 16 bits of fp32 (exact bf16), lo = x - hi
__device__ __forceinline__ void split2t(float x0, float x1, unsigned& hi, unsigned& lo) {
    unsigned u0 = __float_as_uint(x0), u1 = __float_as_uint(x1);
    float h0 = __uint_as_float(u0 & 0xFFFF0000u);
    float h1 = __uint_as_float(u1 & 0xFFFF0000u);
    asm("prmt.b32 %0, %1, %2, 0x7632;" : "=r"(hi) : "r"(u0), "r"(u1));
    asm("cvt.rn.bf16x2.f32 %0, %1, %2;" : "=r"(lo) : "f"(x1 - h1), "f"(x0 - h0));
}
__device__ __forceinline__ float fexp2(float x) {
    float y;
    asm("ex2.approx.f32 %0, %1;" : "=f"(y) : "f"(x));
    return y;
}

// ---------------------------------------------------------------------------
// Convert kernels
// ---------------------------------------------------------------------------
__global__ __launch_bounds__(256) void convert_x_kernel(const float* __restrict__ x)
{
    size_t i = (size_t)blockIdx.x * blockDim.x + threadIdx.x;
    float4 v = ((const float4*)x)[i];
    size_t b = i * 4;
    float vv[4] = {v.x, v.y, v.z, v.w};
#pragma unroll
    for (int j = 0; j < 4; j++) {
        __nv_bfloat16 h = __float2bfloat16(vv[j]);
        __nv_bfloat16 l = __float2bfloat16(vv[j] - __bfloat162float(h));
        g_a_hi[b + j] = h;
        g_a_lo[b + j] = l;
    }
}

__global__ __launch_bounds__(1024) void convert_w_kernel(const float* __restrict__ w)
{
    __shared__ float t[32][33];
    const int n0 = blockIdx.x * 32;
    const int k0 = blockIdx.y * 32;
    const int tx = threadIdx.x, ty = threadIdx.y;
    t[ty][tx] = w[(size_t)(k0 + ty) * GN + n0 + tx];
    __syncthreads();
    float v = t[tx][ty];
    __nv_bfloat16 h = __float2bfloat16(v);
    __nv_bfloat16 l = __float2bfloat16(v - __bfloat162float(h));
    size_t o = (size_t)(n0 + ty) * GK + k0 + tx;
    g_wt_hi[o] = h;
    g_wt_lo[o] = l;
}

// ---------------------------------------------------------------------------
// Kernel 1: persistent QKV GEMM. 296 CTAs x 128 threads (2 CTAs/SM).
// Tile 128x128 per iteration, 4 warps (warp tile 64x64), BK=32,
// 3-MMA hi/lo split, cp.async double buffer (80KB smem/CTA).
// ---------------------------------------------------------------------------
#define GBK     32
#define GRS     40
#define GA      (128 * GRS)             // 5120 halves per array
#define GSTG    (4 * GA)                // Ahi, Alo, Bhi, Blo
#define GSMEM_B (2 * GSTG * 2)          // 81920 bytes
#define GTILE_N (GN / 128)              // 24
#define GTILES  (GTILE_N * (GM / 128))  // 1536
#define GNSTAGE (GK / GBK)              // 32
#define GPERS   296

__device__ __forceinline__ void gemm_load_stage(unsigned sb, int buf, int stage,
                                                int m0, int n0, int tid)
{
    const int k0 = stage * GBK;
    const unsigned stb = sb + (unsigned)(buf * GSTG) * 2;
#pragma unroll
    for (int j = 0; j < 4; j++) {
        const int idx = tid + j * 128;
        const int r = idx >> 2, c16 = idx & 3;
        const unsigned so = stb + (unsigned)(r * GRS + c16 * 8) * 2;
        const size_t ea = (size_t)(m0 + r) * GK + k0 + c16 * 8;
        const size_t eb = (size_t)(n0 + r) * GK + k0 + c16 * 8;
        cp_async16(so,              &g_a_hi[ea]);
        cp_async16(so + GA * 2,     &g_a_lo[ea]);
        cp_async16(so + 2 * GA * 2, &g_wt_hi[eb]);
        cp_async16(so + 3 * GA * 2, &g_wt_lo[eb]);
    }
    cp_commit();
}

__global__ __launch_bounds__(128, 2) void qkv_hmma_kernel(const float* __restrict__ bias)
{
    extern __shared__ __nv_bfloat16 smg[];
    const unsigned sb = smem_u32(smg);

    const int tid  = threadIdx.x;
    const int wid  = tid >> 5;
    const int lane = tid & 31;
    const int wm   = wid & 1;
    const int wn   = wid >> 1;

    const int a_r = lane & 15;
    const int a_c = (lane >> 4) * 8;
    const int b_q = lane >> 3;
    const int b_r = (b_q >> 1) * 8 + (lane & 7);
    const int b_c = (b_q & 1) * 8;

    for (int t = blockIdx.x; t < GTILES; t += GPERS) {
        const int m0 = (t / GTILE_N) * 128;
        const int n0 = (t % GTILE_N) * 128;

        float acc[4][8][4];
#pragma unroll
        for (int i = 0; i < 4; i++)
#pragma unroll
            for (int j = 0; j < 8; j++)
#pragma unroll
                for (int q = 0; q < 4; q++) acc[i][j][q] = 0.f;

        gemm_load_stage(sb, 0, 0, m0, n0, tid);

        for (int st = 0; st < GNSTAGE; st++) {
            const int s = st & 1;
            if (st + 1 < GNSTAGE) {
                gemm_load_stage(sb, (st + 1) & 1, st + 1, m0, n0, tid);
                cp_wait<1>();
            } else {
                cp_wait<0>();
            }
            __syncthreads();

            const unsigned stb = sb + (unsigned)(s * GSTG) * 2;

#pragma unroll
            for (int ks = 0; ks < 2; ks++) {
                const int kh = ks * 16;

                unsigned ah[4][4], al[4][4];
#pragma unroll
                for (int i = 0; i < 4; i++) {
                    const int row = wm * 64 + i * 16 + a_r;
                    const unsigned off = (unsigned)(row * GRS + kh + a_c) * 2;
                    ldmx4(ah[i][0], ah[i][1], ah[i][2], ah[i][3], stb + off);
                    ldmx4(al[i][0], al[i][1], al[i][2], al[i][3], stb + GA * 2 + off);
                }
                unsigned bh[4][4], bl[4][4];
#pragma unroll
                for (int g = 0; g < 4; g++) {
                    const int nrow = wn * 64 + g * 16 + b_r;
                    const unsigned off = (unsigned)(nrow * GRS + kh + b_c) * 2;
                    ldmx4(bh[g][0], bh[g][1], bh[g][2], bh[g][3],
                          stb + 2 * GA * 2 + off);
                    ldmx4(bl[g][0], bl[g][1], bl[g][2], bl[g][3],
                          stb + 3 * GA * 2 + off);
                }

#pragma unroll
                for (int i = 0; i < 4; i++) {
#pragma unroll
                    for (int j = 0; j < 8; j++) {
                        const int g = j >> 1, js = (j & 1) * 2;
                        mma_bf16(acc[i][j], ah[i][0], ah[i][1], ah[i][2], ah[i][3],
                                 bh[g][js], bh[g][js + 1]);
                        mma_bf16(acc[i][j], ah[i][0], ah[i][1], ah[i][2], ah[i][3],
                                 bl[g][js], bl[g][js + 1]);
                        mma_bf16(acc[i][j], al[i][0], al[i][1], al[i][2], al[i][3],
                                 bh[g][js], bh[g][js + 1]);
                    }
                }
            }
            __syncthreads();
        }

        // Epilogue
        const int sec = n0 >> 10;                     // 0=K, 1=Q, 2=V
        __nv_bfloat16* dh = (sec == 0) ? g_kh : (sec == 1) ? g_qh : g_vh;
        __nv_bfloat16* dl = (sec == 0) ? g_kl : (sec == 1) ? g_ql : g_vl;
        const float sc = (sec == 1) ? QSCALE : 1.0f;

        const int lr = lane >> 2;
        const int lc = (lane & 3) * 2;
#pragma unroll
        for (int j = 0; j < 8; j++) {
            const int gcol = n0 + wn * 64 + j * 8 + lc;
            const float b0 = __ldg(&bias[gcol]);
            const float b1 = __ldg(&bias[gcol + 1]);
            const int ccol = gcol & 1023;
#pragma unroll
            for (int i = 0; i < 4; i++) {
                const int row = m0 + wm * 64 + i * 16 + lr;
                float v00 = (acc[i][j][0] + b0) * sc;
                float v01 = (acc[i][j][1] + b1) * sc;
                float v10 = (acc[i][j][2] + b0) * sc;
                float v11 = (acc[i][j][3] + b1) * sc;
                unsigned h0, l0, h1, l1;
                split2(v00, v01, h0, l0);
                split2(v10, v11, h1, l1);
                *(unsigned*)&dh[(size_t)row * CC + ccol]       = h0;
                *(unsigned*)&dh[(size_t)(row + 8) * CC + ccol] = h1;
                *(unsigned*)&dl[(size_t)row * CC + ccol]       = l0;
                *(unsigned*)&dl[(size_t)(row + 8) * CC + ccol] = l1;
            }
        }
    }
}

// ---------------------------------------------------------------------------
// Kernel 2: causal flash attention on HMMA.
// CTA: 128 threads (4 warps), 64 queries x one (b,h); 2 CTAs/SM.
// Fixed-shift base-2 softmax. Half-tile software pipeline:
//   S_a, S_b, softmax_a, PV_a, softmax_b, PV_b
// so every dependency wait has the warp's own MMAs draining behind it.
// ---------------------------------------------------------------------------
#define AT_RS   72
#define AQ_ARR  (64 * AT_RS)
#define AKV_OFF (2 * AQ_ARR)
#define AKV_ARR (64 * AT_RS)
#define AKV_STG (4 * AKV_ARR)
#define ASM_HALVES (AKV_OFF + 2 * AKV_STG)   // 46080 halves = 92160 B

__device__ __forceinline__ void attn_load_kv(unsigned sb, int buf, size_t rowbase,
                                             int k0, int tid)
{
#pragma unroll
    for (int j = 0; j < 16; j++) {
        const int idx = tid + j * 128;
        const int arr = idx >> 9;            // 0=kh 1=kl 2=vh 3=vl
        const int w = idx & 511;
        const int r = w >> 3, c = w & 7;
        const __nv_bfloat16* src =
            (arr == 0 ? g_kh : arr == 1 ? g_kl : arr == 2 ? g_vh : g_vl)
            + rowbase + (size_t)(k0 + r) * CC + c * 8;
        const unsigned dst = sb +
            (unsigned)(AKV_OFF + buf * AKV_STG + arr * AKV_ARR + r * AT_RS + c * 8) * 2;
        cp_async16(dst, src);
    }
    cp_commit();
}

__global__ __launch_bounds__(128, 2) void attn_hmma_kernel(float* __restrict__ out)
{
    extern __shared__ __nv_bfloat16 sma[];
    const unsigned sb = smem_u32(sma);

    const int tid  = threadIdx.x;
    const int wq   = tid >> 5;
    const int lane = tid & 31;
    const int qb   = (gridDim.x - 1) - blockIdx.x;   // heavy blocks first
    const int bh   = blockIdx.y;
    const int b    = bh >> 4;
    const int h    = bh & 15;
    const int q0   = qb * 64;

    const size_t rowbase = (size_t)b * TT * CC + h * DD;

    // Q staging (qh + ql)
#pragma unroll
    for (int j = 0; j < 8; j++) {
        const int idx = tid + j * 128;
        const int arr = idx >> 9;
        const int w = idx & 511;
        const int r = w >> 3, c = w & 7;
        const __nv_bfloat16* src = (arr ? g_ql : g_qh)
            + rowbase + (size_t)(q0 + r) * CC + c * 8;
        cp_async16(sb + (unsigned)(arr * AQ_ARR + r * AT_RS + c * 8) * 2, src);
    }
    cp_commit();

    attn_load_kv(sb, 0, rowbase, 0, tid);

    float o[8][4];
#pragma unroll
    for (int j = 0; j < 8; j++)
#pragma unroll
        for (int e = 0; e < 4; e++) o[j][e] = 0.f;
    float l0 = 0.f, l1 = 0.f;

    unsigned qh[4][4], ql[4][4];

    const int r0g = q0 + wq * 16 + (lane >> 2);
    const int r1g = r0g + 8;
    const int colq = 2 * (lane & 3);

    const int ntiles = qb + 1;

    for (int t = 0; t < ntiles; t++) {
        if (t + 1 < ntiles) {
            attn_load_kv(sb, (t + 1) & 1, rowbase, (t + 1) * 64, tid);
            cp_wait<1>();
        } else {
            cp_wait<0>();
        }
        __syncthreads();

        if (t == 0) {
#pragma unroll
            for (int kt = 0; kt < 4; kt++) {
                const unsigned off = (unsigned)((wq * 16 + (lane & 15)) * AT_RS
                                                + kt * 16 + (lane >> 4) * 8) * 2;
                ldmx4(qh[kt][0], qh[kt][1], qh[kt][2], qh[kt][3], sb + off);
                ldmx4(ql[kt][0], ql[kt][1], ql[kt][2], ql[kt][3],
                      sb + (unsigned)(AQ_ARR) * 2 + off);
            }
        }

        const unsigned kvb = sb + (unsigned)(AKV_OFF + (t & 1) * AKV_STG) * 2;
        const int kbase = t * 64;
        const bool diag = (t == ntiles - 1);

        // ---- S = Q K^T, half a (keys 0-31) then half b (keys 32-63) ----
        float s[8][4];
#pragma unroll
        for (int j = 0; j < 8; j++)
#pragma unroll
            for (int e = 0; e < 4; e++) s[j][e] = 0.f;

#pragma unroll
        for (int ng = 0; ng < 4; ng++) {          // ng outer: half a = ng 0,1
#pragma unroll
            for (int kt = 0; kt < 4; kt++) {
                const unsigned roff = (unsigned)(
                    (ng * 16 + ((lane >> 4) & 1) * 8 + (lane & 7)) * AT_RS
                    + kt * 16 + ((lane >> 3) & 1) * 8) * 2;
                unsigned k0r, k1r, k2r, k3r, c0r, c1r, c2r, c3r;
                ldmx4(k0r, k1r, k2r, k3r, kvb + 0 * AKV_ARR * 2 + roff);
                ldmx4(c0r, c1r, c2r, c3r, kvb + 1 * AKV_ARR * 2 + roff);
                mma_bf16(s[2 * ng], qh[kt][0], qh[kt][1], qh[kt][2], qh[kt][3], k0r, k1r);
                mma_bf16(s[2 * ng], qh[kt][0], qh[kt][1], qh[kt][2], qh[kt][3], c0r, c1r);
                mma_bf16(s[2 * ng], ql[kt][0], ql[kt][1], ql[kt][2], ql[kt][3], k0r, k1r);
                mma_bf16(s[2 * ng + 1], qh[kt][0], qh[kt][1], qh[kt][2], qh[kt][3], k2r, k3r);
                mma_bf16(s[2 * ng + 1], qh[kt][0], qh[kt][1], qh[kt][2], qh[kt][3], c2r, c3r);
                mma_bf16(s[2 * ng + 1], ql[kt][0], ql[kt][1], ql[kt][2], ql[kt][3], k2r, k3r);
            }
        }

        // ======== half a: softmax (j=0..3) + PV (key groups kt=0,1) ========
        {
            if (diag) {
#pragma unroll
                for (int j = 0; j < 4; j++) {
                    const int cb = kbase + j * 8 + colq;
#pragma unroll
                    for (int e = 0; e < 2; e++) {
                        const int col = cb + e;
                        if (col > r0g) s[j][e]     = -CUDART_INF_F;
                        if (col > r1g) s[j][2 + e] = -CUDART_INF_F;
                    }
                }
            }
#pragma unroll
            for (int j = 0; j < 4; j++) {
                float p0 = fexp2(s[j][0]);
                float p1 = fexp2(s[j][1]);
                float p2 = fexp2(s[j][2]);
                float p3 = fexp2(s[j][3]);
                l0 += p0 + p1; l1 += p2 + p3;
                s[j][0] = p0; s[j][1] = p1; s[j][2] = p2; s[j][3] = p3;
            }
#pragma unroll
            for (int kt = 0; kt < 2; kt++) {
                unsigned pa0h, pa0l, pa1h, pa1l, pa2h, pa2l, pa3h, pa3l;
                split2t(s[2 * kt][0],     s[2 * kt][1],     pa0h, pa0l);
                split2t(s[2 * kt][2],     s[2 * kt][3],     pa1h, pa1l);
                split2t(s[2 * kt + 1][0], s[2 * kt + 1][1], pa2h, pa2l);
                split2t(s[2 * kt + 1][2], s[2 * kt + 1][3], pa3h, pa3l);
#pragma unroll
                for (int ng = 0; ng < 4; ng++) {
                    const unsigned voff = (unsigned)(
                        (kt * 16 + ((lane >> 3) & 1) * 8 + (lane & 7)) * AT_RS
                        + ng * 16 + (lane >> 4) * 8) * 2;
                    unsigned v0r, v1r, v2r, v3r, w0r, w1r, w2r, w3r;
                    ldmx4t(v0r, v1r, v2r, v3r, kvb + 2 * AKV_ARR * 2 + voff);
                    ldmx4t(w0r, w1r, w2r, w3r, kvb + 3 * AKV_ARR * 2 + voff);
                    mma_bf16(o[2 * ng],     pa0h, pa1h, pa2h, pa3h, v0r, v1r);
                    mma_bf16(o[2 * ng],     pa0h, pa1h, pa2h, pa3h, w0r, w1r);
                    mma_bf16(o[2 * ng],     pa0l, pa1l, pa2l, pa3l, v0r, v1r);
                    mma_bf16(o[2 * ng + 1], pa0h, pa1h, pa2h, pa3h, v2r, v3r);
                    mma_bf16(o[2 * ng + 1], pa0h, pa1h, pa2h, pa3h, w2r, w3r);
                    mma_bf16(o[2 * ng + 1], pa0l, pa1l, pa2l, pa3l, v2r, v3r);
                }
            }
        }

        // ======== half b: softmax (j=4..7) + PV (key groups kt=2,3) ========
        {
            if (diag) {
#pragma unroll
                for (int j = 4; j < 8; j++) {
                    const int cb = kbase + j * 8 + colq;
#pragma unroll
                    for (int e = 0; e < 2; e++) {
                        const int col = cb + e;
                        if (col > r0g) s[j][e]     = -CUDART_INF_F;
                        if (col > r1g) s[j][2 + e] = -CUDART_INF_F;
                    }
                }
            }
#pragma unroll
            for (int j = 4; j < 8; j++) {
                float p0 = fexp2(s[j][0]);
                float p1 = fexp2(s[j][1]);
                float p2 = fexp2(s[j][2]);
                float p3 = fexp2(s[j][3]);
                l0 += p0 + p1; l1 += p2 + p3;
                s[j][0] = p0; s[j][1] = p1; s[j][2] = p2; s[j][3] = p3;
            }
#pragma unroll
            for (int kt = 2; kt < 4; kt++) {
                unsigned pa0h, pa0l, pa1h, pa1l, pa2h, pa2l, pa3h, pa3l;
                split2t(s[2 * kt][0],     s[2 * kt][1],     pa0h, pa0l);
                split2t(s[2 * kt][2],     s[2 * kt][3],     pa1h, pa1l);
                split2t(s[2 * kt + 1][0], s[2 * kt + 1][1], pa2h, pa2l);
                split2t(s[2 * kt + 1][2], s[2 * kt + 1][3], pa3h, pa3l);
#pragma unroll
                for (int ng = 0; ng < 4; ng++) {
                    const unsigned voff = (unsigned)(
                        (kt * 16 + ((lane >> 3) & 1) * 8 + (lane & 7)) * AT_RS
                        + ng * 16 + (lane >> 4) * 8) * 2;
                    unsigned v0r, v1r, v2r, v3r, w0r, w1r, w2r, w3r;
                    ldmx4t(v0r, v1r, v2r, v3r, kvb + 2 * AKV_ARR * 2 + voff);
                    ldmx4t(w0r, w1r, w2r, w3r, kvb + 3 * AKV_ARR * 2 + voff);
                    mma_bf16(o[2 * ng],     pa0h, pa1h, pa2h, pa3h, v0r, v1r);
                    mma_bf16(o[2 * ng],     pa0h, pa1h, pa2h, pa3h, w0r, w1r);
                    mma_bf16(o[2 * ng],     pa0l, pa1l, pa2l, pa3l, v0r, v1r);
                    mma_bf16(o[2 * ng + 1], pa0h, pa1h, pa2h, pa3h, v2r, v3r);
                    mma_bf16(o[2 * ng + 1], pa0h, pa1h, pa2h, pa3h, w2r, w3r);
                    mma_bf16(o[2 * ng + 1], pa0l, pa1l, pa2l, pa3l, v2r, v3r);
                }
            }
        }
        __syncthreads();
    }

    // ---- finalize ----
    l0 += __shfl_xor_sync(0xffffffffu, l0, 1);
    l0 += __shfl_xor_sync(0xffffffffu, l0, 2);
    l1 += __shfl_xor_sync(0xffffffffu, l1, 1);
    l1 += __shfl_xor_sync(0xffffffffu, l1, 2);
    const float inv0 = 1.f / l0;
    const float inv1 = 1.f / l1;

    float* row0 = out + ((size_t)b * TT + r0g) * CC + h * DD;
    float* row1 = out + ((size_t)b * TT + r1g) * CC + h * DD;
#pragma unroll
    for (int j = 0; j < 8; j++) {
        const int c = j * 8 + colq;
        *(float2*)&row0[c] = make_float2(o[j][0] * inv0, o[j][1] * inv0);
        *(float2*)&row1[c] = make_float2(o[j][2] * inv1, o[j][3] * inv1);
    }
}

// ---------------------------------------------------------------------------
extern "C" void kernel_launch(void* const* d_in, const int* in_sizes, int n_in,
                              void* d_out, int out_size)
{
    const float* x    = (const float*)d_in[0];   // [B,T,C]
    const float* w    = (const float*)d_in[1];   // [C, 3C]
    const float* bias = (const float*)d_in[2];   // [3C]
    float* out = (float*)d_out;                  // [B,T,C]

    convert_x_kernel<<<(GM * GK / 4) / 256, 256>>>(x);
    dim3 wgrid(GN / 32, GK / 32);
    convert_w_kernel<<<wgrid, dim3(32, 32)>>>(w);

    cudaFuncSetAttribute(qkv_hmma_kernel,
                         cudaFuncAttributeMaxDynamicSharedMemorySize, GSMEM_B);
    qkv_hmma_kernel<<<GPERS, 128, GSMEM_B>>>(bias);

    const int kAttnSmem = ASM_HALVES * 2;        // 92160 B
    cudaFuncSetAttribute(attn_hmma_kernel,
                         cudaFuncAttributeMaxDynamicSharedMemorySize, kAttnSmem);
    dim3 agrid(TT / 64, BB * HH);                // (32, 64)
    attn_hmma_kernel<<<agrid, 128, kAttnSmem>>>(out);
}

// round 16
// speedup vs baseline: 1.0027x; 1.0027x over previous
#include <cuda_runtime.h>
#include <cuda_bf16.h>
#include <math_constants.h>

// Problem constants
#define BB   4
#define TT   2048
#define CC   1024
#define HH   16
#define DD   64
#define GM   (BB*TT)      // 8192
#define GK   CC           // 1024
#define GN   (3*CC)       // 3072

// ---------------------------------------------------------------------------
// Device scratch (no allocs allowed)
// ---------------------------------------------------------------------------
__device__ __align__(128) __nv_bfloat16 g_a_hi[(size_t)GM * GK];
__device__ __align__(128) __nv_bfloat16 g_a_lo[(size_t)GM * GK];
__device__ __align__(128) __nv_bfloat16 g_wt_hi[(size_t)GN * GK];       // W^T
__device__ __align__(128) __nv_bfloat16 g_wt_lo[(size_t)GN * GK];
// QKV results as bf16 hi/lo per section
__device__ __align__(128) __nv_bfloat16 g_kh[(size_t)GM * CC];
__device__ __align__(128) __nv_bfloat16 g_kl[(size_t)GM * CC];
__device__ __align__(128) __nv_bfloat16 g_qh[(size_t)GM * CC];          // pre-scaled
__device__ __align__(128) __nv_bfloat16 g_ql[(size_t)GM * CC];
__device__ __align__(128) __nv_bfloat16 g_vh[(size_t)GM * CC];
__device__ __align__(128) __nv_bfloat16 g_vl[(size_t)GM * CC];

// Q pre-scale: (1/sqrt(64)) * log2(e)  -> softmax computed base-2
#define QSCALE 0.18033688011112042f

// ---------------------------------------------------------------------------
// Portable PTX helpers (sm_80+)
// ---------------------------------------------------------------------------
__device__ __forceinline__ unsigned smem_u32(const void* p) {
    unsigned a;
    asm("{ .reg .u64 t; cvta.to.shared.u64 t, %1; cvt.u32.u64 %0, t; }"
        : "=r"(a) : "l"(p));
    return a;
}
__device__ __forceinline__ void cp_async16(unsigned dst, const void* src) {
    asm volatile("cp.async.cg.shared.global [%0], [%1], 16;"
                 :: "r"(dst), "l"(src) : "memory");
}
__device__ __forceinline__ void cp_commit() {
    asm volatile("cp.async.commit_group;" ::: "memory");
}
template <int N>
__device__ __forceinline__ void cp_wait() {
    asm volatile("cp.async.wait_group %0;" :: "n"(N) : "memory");
}
__device__ __forceinline__ void ldmx4(unsigned& r0, unsigned& r1, unsigned& r2,
                                      unsigned& r3, unsigned addr) {
    asm volatile("ldmatrix.sync.aligned.m8n8.x4.shared.b16 {%0,%1,%2,%3}, [%4];"
                 : "=r"(r0), "=r"(r1), "=r"(r2), "=r"(r3) : "r"(addr));
}
__device__ __forceinline__ void ldmx4t(unsigned& r0, unsigned& r1, unsigned& r2,
                                       unsigned& r3, unsigned addr) {
    asm volatile("ldmatrix.sync.aligned.m8n8.x4.trans.shared.b16 {%0,%1,%2,%3}, [%4];"
                 : "=r"(r0), "=r"(r1), "=r"(r2), "=r"(r3) : "r"(addr));
}
__device__ __forceinline__ void mma_bf16(float* c, unsigned a0, unsigned a1,
                                         unsigned a2, unsigned a3,
                                         unsigned b0, unsigned b1) {
    asm volatile(
        "mma.sync.aligned.m16n8k16.row.col.f32.bf16.bf16.f32 "
        "{%0,%1,%2,%3}, {%4,%5,%6,%7}, {%8,%9}, {%0,%1,%2,%3};"
        : "+f"(c[0]), "+f"(c[1]), "+f"(c[2]), "+f"(c[3])
        : "r"(a0), "r"(a1), "r"(a2), "r"(a3), "r"(b0), "r"(b1));
}
// round-nearest split (used in GEMM epilogue)
__device__ __forceinline__ void split2(float x0, float x1, unsigned& hi, unsigned& lo) {
    __nv_bfloat16 h0 = __float2bfloat16(x0), h1 = __float2bfloat16(x1);
    float r0 = x0 - __bfloat162float(h0), r1 = x1 - __bfloat162float(h1);
    __nv_bfloat162 hv; hv.x = h0; hv.y = h1;
    __nv_bfloat162 lv; lv.x = __float2bfloat16(r0); lv.y = __float2bfloat16(r1);
    hi = *(unsigned*)&hv; lo = *(unsigned*)&lv;
}
// truncation split: hi = top 16 bits of fp32 (exact bf16), lo = x - hi
__device__ __forceinline__ void split2t(float x0, float x1, unsigned& hi, unsigned& lo) {
    unsigned u0 = __float_as_uint(x0), u1 = __float_as_uint(x1);
    float h0 = __uint_as_float(u0 & 0xFFFF0000u);
    float h1 = __uint_as_float(u1 & 0xFFFF0000u);
    asm("prmt.b32 %0, %1, %2, 0x7632;" : "=r"(hi) : "r"(u0), "r"(u1));
    asm("cvt.rn.bf16x2.f32 %0, %1, %2;" : "=r"(lo) : "f"(x1 - h1), "f"(x0 - h0));
}
__device__ __forceinline__ float fexp2(float x) {
    float y;
    asm("ex2.approx.f32 %0, %1;" : "=f"(y) : "f"(x));
    return y;
}

// ---------------------------------------------------------------------------
// Convert kernels
// ---------------------------------------------------------------------------
__global__ __launch_bounds__(256) void convert_x_kernel(const float* __restrict__ x)
{
    size_t i = (size_t)blockIdx.x * blockDim.x + threadIdx.x;
    float4 v = ((const float4*)x)[i];
    size_t b = i * 4;
    float vv[4] = {v.x, v.y, v.z, v.w};
#pragma unroll
    for (int j = 0; j < 4; j++) {
        __nv_bfloat16 h = __float2bfloat16(vv[j]);
        __nv_bfloat16 l = __float2bfloat16(vv[j] - __bfloat162float(h));
        g_a_hi[b + j] = h;
        g_a_lo[b + j] = l;
    }
}

__global__ __launch_bounds__(1024) void convert_w_kernel(const float* __restrict__ w)
{
    __shared__ float t[32][33];
    const int n0 = blockIdx.x * 32;
    const int k0 = blockIdx.y * 32;
    const int tx = threadIdx.x, ty = threadIdx.y;
    t[ty][tx] = w[(size_t)(k0 + ty) * GN + n0 + tx];
    __syncthreads();
    float v = t[tx][ty];
    __nv_bfloat16 h = __float2bfloat16(v);
    __nv_bfloat16 l = __float2bfloat16(v - __bfloat162float(h));
    size_t o = (size_t)(n0 + ty) * GK + k0 + tx;
    g_wt_hi[o] = h;
    g_wt_lo[o] = l;
}

// ---------------------------------------------------------------------------
// Kernel 1: persistent QKV GEMM. 296 CTAs x 128 threads (2 CTAs/SM).
// Tile 128x128 per iteration, 4 warps (warp tile 64x64), BK=32,
// 3-MMA hi/lo split, cp.async double buffer (80KB smem/CTA).
// ---------------------------------------------------------------------------
#define GBK     32
#define GRS     40
#define GA      (128 * GRS)             // 5120 halves per array
#define GSTG    (4 * GA)                // Ahi, Alo, Bhi, Blo
#define GSMEM_B (2 * GSTG * 2)          // 81920 bytes
#define GTILE_N (GN / 128)              // 24
#define GTILES  (GTILE_N * (GM / 128))  // 1536
#define GNSTAGE (GK / GBK)              // 32
#define GPERS   296

__device__ __forceinline__ void gemm_load_stage(unsigned sb, int buf, int stage,
                                                int m0, int n0, int tid)
{
    const int k0 = stage * GBK;
    const unsigned stb = sb + (unsigned)(buf * GSTG) * 2;
#pragma unroll
    for (int j = 0; j < 4; j++) {
        const int idx = tid + j * 128;
        const int r = idx >> 2, c16 = idx & 3;
        const unsigned so = stb + (unsigned)(r * GRS + c16 * 8) * 2;
        const size_t ea = (size_t)(m0 + r) * GK + k0 + c16 * 8;
        const size_t eb = (size_t)(n0 + r) * GK + k0 + c16 * 8;
        cp_async16(so,              &g_a_hi[ea]);
        cp_async16(so + GA * 2,     &g_a_lo[ea]);
        cp_async16(so + 2 * GA * 2, &g_wt_hi[eb]);
        cp_async16(so + 3 * GA * 2, &g_wt_lo[eb]);
    }
    cp_commit();
}

__global__ __launch_bounds__(128, 2) void qkv_hmma_kernel(const float* __restrict__ bias)
{
    extern __shared__ __nv_bfloat16 smg[];
    const unsigned sb = smem_u32(smg);

    const int tid  = threadIdx.x;
    const int wid  = tid >> 5;
    const int lane = tid & 31;
    const int wm   = wid & 1;
    const int wn   = wid >> 1;

    const int a_r = lane & 15;
    const int a_c = (lane >> 4) * 8;
    const int b_q = lane >> 3;
    const int b_r = (b_q >> 1) * 8 + (lane & 7);
    const int b_c = (b_q & 1) * 8;

    for (int t = blockIdx.x; t < GTILES; t += GPERS) {
        const int m0 = (t / GTILE_N) * 128;
        const int n0 = (t % GTILE_N) * 128;

        float acc[4][8][4];
#pragma unroll
        for (int i = 0; i < 4; i++)
#pragma unroll
            for (int j = 0; j < 8; j++)
#pragma unroll
                for (int q = 0; q < 4; q++) acc[i][j][q] = 0.f;

        gemm_load_stage(sb, 0, 0, m0, n0, tid);

        for (int st = 0; st < GNSTAGE; st++) {
            const int s = st & 1;
            if (st + 1 < GNSTAGE) {
                gemm_load_stage(sb, (st + 1) & 1, st + 1, m0, n0, tid);
                cp_wait<1>();
            } else {
                cp_wait<0>();
            }
            __syncthreads();

            const unsigned stb = sb + (unsigned)(s * GSTG) * 2;

#pragma unroll
            for (int ks = 0; ks < 2; ks++) {
                const int kh = ks * 16;

                unsigned ah[4][4], al[4][4];
#pragma unroll
                for (int i = 0; i < 4; i++) {
                    const int row = wm * 64 + i * 16 + a_r;
                    const unsigned off = (unsigned)(row * GRS + kh + a_c) * 2;
                    ldmx4(ah[i][0], ah[i][1], ah[i][2], ah[i][3], stb + off);
                    ldmx4(al[i][0], al[i][1], al[i][2], al[i][3], stb + GA * 2 + off);
                }
                unsigned bh[4][4], bl[4][4];
#pragma unroll
                for (int g = 0; g < 4; g++) {
                    const int nrow = wn * 64 + g * 16 + b_r;
                    const unsigned off = (unsigned)(nrow * GRS + kh + b_c) * 2;
                    ldmx4(bh[g][0], bh[g][1], bh[g][2], bh[g][3],
                          stb + 2 * GA * 2 + off);
                    ldmx4(bl[g][0], bl[g][1], bl[g][2], bl[g][3],
                          stb + 3 * GA * 2 + off);
                }

#pragma unroll
                for (int i = 0; i < 4; i++) {
#pragma unroll
                    for (int j = 0; j < 8; j++) {
                        const int g = j >> 1, js = (j & 1) * 2;
                        mma_bf16(acc[i][j], ah[i][0], ah[i][1], ah[i][2], ah[i][3],
                                 bh[g][js], bh[g][js + 1]);
                        mma_bf16(acc[i][j], ah[i][0], ah[i][1], ah[i][2], ah[i][3],
                                 bl[g][js], bl[g][js + 1]);
                        mma_bf16(acc[i][j], al[i][0], al[i][1], al[i][2], al[i][3],
                                 bh[g][js], bh[g][js + 1]);
                    }
                }
            }
            __syncthreads();
        }

        // Epilogue
        const int sec = n0 >> 10;                     // 0=K, 1=Q, 2=V
        __nv_bfloat16* dh = (sec == 0) ? g_kh : (sec == 1) ? g_qh : g_vh;
        __nv_bfloat16* dl = (sec == 0) ? g_kl : (sec == 1) ? g_ql : g_vl;
        const float sc = (sec == 1) ? QSCALE : 1.0f;

        const int lr = lane >> 2;
        const int lc = (lane & 3) * 2;
#pragma unroll
        for (int j = 0; j < 8; j++) {
            const int gcol = n0 + wn * 64 + j * 8 + lc;
            const float b0 = __ldg(&bias[gcol]);
            const float b1 = __ldg(&bias[gcol + 1]);
            const int ccol = gcol & 1023;
#pragma unroll
            for (int i = 0; i < 4; i++) {
                const int row = m0 + wm * 64 + i * 16 + lr;
                float v00 = (acc[i][j][0] + b0) * sc;
                float v01 = (acc[i][j][1] + b1) * sc;
                float v10 = (acc[i][j][2] + b0) * sc;
                float v11 = (acc[i][j][3] + b1) * sc;
                unsigned h0, l0, h1, l1;
                split2(v00, v01, h0, l0);
                split2(v10, v11, h1, l1);
                *(unsigned*)&dh[(size_t)row * CC + ccol]       = h0;
                *(unsigned*)&dh[(size_t)(row + 8) * CC + ccol] = h1;
                *(unsigned*)&dl[(size_t)row * CC + ccol]       = l0;
                *(unsigned*)&dl[(size_t)(row + 8) * CC + ccol] = l1;
            }
        }
    }
}

// ---------------------------------------------------------------------------
// Kernel 2: causal flash attention on HMMA.
// CTA: 128 threads (4 warps), 64 queries x one (b,h); 3 CTAs/SM.
// Q fragments loaded directly from global (no Q smem staging -> smem fits
// 3 CTAs/SM). KV hi/lo double-buffered in smem. Fixed-shift base-2 softmax,
// half-tile pipeline, diagonal-tile-only masking, truncation split for P.
// ---------------------------------------------------------------------------
#define AT_RS   72
#define AKV_ARR (64 * AT_RS)
#define AKV_STG (4 * AKV_ARR)
#define ASM_HALVES (2 * AKV_STG)          // 36864 halves = 73728 B

__device__ __forceinline__ void attn_load_kv(unsigned sb, int buf, size_t rowbase,
                                             int k0, int tid)
{
#pragma unroll
    for (int j = 0; j < 16; j++) {
        const int idx = tid + j * 128;
        const int arr = idx >> 9;            // 0=kh 1=kl 2=vh 3=vl
        const int w = idx & 511;
        const int r = w >> 3, c = w & 7;
        const __nv_bfloat16* src =
            (arr == 0 ? g_kh : arr == 1 ? g_kl : arr == 2 ? g_vh : g_vl)
            + rowbase + (size_t)(k0 + r) * CC + c * 8;
        const unsigned dst = sb +
            (unsigned)(buf * AKV_STG + arr * AKV_ARR + r * AT_RS + c * 8) * 2;
        cp_async16(dst, src);
    }
    cp_commit();
}

__global__ __launch_bounds__(128, 3) void attn_hmma_kernel(float* __restrict__ out)
{
    extern __shared__ __nv_bfloat16 sma[];
    const unsigned sb = smem_u32(sma);

    const int tid  = threadIdx.x;
    const int wq   = tid >> 5;
    const int lane = tid & 31;
    const int qb   = (gridDim.x - 1) - blockIdx.x;   // heavy blocks first
    const int bh   = blockIdx.y;
    const int b    = bh >> 4;
    const int h    = bh & 15;
    const int q0   = qb * 64;

    const size_t rowbase = (size_t)b * TT * CC + h * DD;

    attn_load_kv(sb, 0, rowbase, 0, tid);

    // ---- Q fragments directly from global (m16n8k16 A-fragment layout):
    //   a0: row=lane>>2,  cols 2*(lane&3)+{0,1} of this kt's 16-col chunk
    //   a1: row+8 same cols;  a2/a3: cols+8.
    unsigned qh[4][4], ql[4][4];
    {
        const int qrow0 = q0 + wq * 16 + (lane >> 2);
        const size_t qb0 = rowbase + (size_t)qrow0 * CC;
        const size_t qb1 = qb0 + 8 * CC;
#pragma unroll
        for (int kt = 0; kt < 4; kt++) {
            const int c0 = kt * 16 + 2 * (lane & 3);
            qh[kt][0] = *(const unsigned*)&g_qh[qb0 + c0];
            qh[kt][1] = *(const unsigned*)&g_qh[qb1 + c0];
            qh[kt][2] = *(const unsigned*)&g_qh[qb0 + c0 + 8];
            qh[kt][3] = *(const unsigned*)&g_qh[qb1 + c0 + 8];
            ql[kt][0] = *(const unsigned*)&g_ql[qb0 + c0];
            ql[kt][1] = *(const unsigned*)&g_ql[qb1 + c0];
            ql[kt][2] = *(const unsigned*)&g_ql[qb0 + c0 + 8];
            ql[kt][3] = *(const unsigned*)&g_ql[qb1 + c0 + 8];
        }
    }

    float o[8][4];
#pragma unroll
    for (int j = 0; j < 8; j++)
#pragma unroll
        for (int e = 0; e < 4; e++) o[j][e] = 0.f;
    float l0 = 0.f, l1 = 0.f;

    const int r0g = q0 + wq * 16 + (lane >> 2);
    const int r1g = r0g + 8;
    const int colq = 2 * (lane & 3);

    const int ntiles = qb + 1;

    for (int t = 0; t < ntiles; t++) {
        if (t + 1 < ntiles) {
            attn_load_kv(sb, (t + 1) & 1, rowbase, (t + 1) * 64, tid);
            cp_wait<1>();
        } else {
            cp_wait<0>();
        }
        __syncthreads();

        const unsigned kvb = sb + (unsigned)((t & 1) * AKV_STG) * 2;
        const int kbase = t * 64;
        const bool diag = (t == ntiles - 1);

        // ---- S = Q K^T, half a (keys 0-31) then half b (keys 32-63) ----
        float s[8][4];
#pragma unroll
        for (int j = 0; j < 8; j++)
#pragma unroll
            for (int e = 0; e < 4; e++) s[j][e] = 0.f;

#pragma unroll
        for (int ng = 0; ng < 4; ng++) {
#pragma unroll
            for (int kt = 0; kt < 4; kt++) {
                const unsigned roff = (unsigned)(
                    (ng * 16 + ((lane >> 4) & 1) * 8 + (lane & 7)) * AT_RS
                    + kt * 16 + ((lane >> 3) & 1) * 8) * 2;
                unsigned k0r, k1r, k2r, k3r, c0r, c1r, c2r, c3r;
                ldmx4(k0r, k1r, k2r, k3r, kvb + 0 * AKV_ARR * 2 + roff);
                ldmx4(c0r, c1r, c2r, c3r, kvb + 1 * AKV_ARR * 2 + roff);
                mma_bf16(s[2 * ng], qh[kt][0], qh[kt][1], qh[kt][2], qh[kt][3], k0r, k1r);
                mma_bf16(s[2 * ng], qh[kt][0], qh[kt][1], qh[kt][2], qh[kt][3], c0r, c1r);
                mma_bf16(s[2 * ng], ql[kt][0], ql[kt][1], ql[kt][2], ql[kt][3], k0r, k1r);
                mma_bf16(s[2 * ng + 1], qh[kt][0], qh[kt][1], qh[kt][2], qh[kt][3], k2r, k3r);
                mma_bf16(s[2 * ng + 1], qh[kt][0], qh[kt][1], qh[kt][2], qh[kt][3], c2r, c3r);
                mma_bf16(s[2 * ng + 1], ql[kt][0], ql[kt][1], ql[kt][2], ql[kt][3], k2r, k3r);
            }
        }

        // ======== half a: softmax (j=0..3) + PV (key groups kt=0,1) ========
        {
            if (diag) {
#pragma unroll
                for (int j = 0; j < 4; j++) {
                    const int cb = kbase + j * 8 + colq;
#pragma unroll
                    for (int e = 0; e < 2; e++) {
                        const int col = cb + e;
                        if (col > r0g) s[j][e]     = -CUDART_INF_F;
                        if (col > r1g) s[j][2 + e] = -CUDART_INF_F;
                    }
                }
            }
#pragma unroll
            for (int j = 0; j < 4; j++) {
                float p0 = fexp2(s[j][0]);
                float p1 = fexp2(s[j][1]);
                float p2 = fexp2(s[j][2]);
                float p3 = fexp2(s[j][3]);
                l0 += p0 + p1; l1 += p2 + p3;
                s[j][0] = p0; s[j][1] = p1; s[j][2] = p2; s[j][3] = p3;
            }
#pragma unroll
            for (int kt = 0; kt < 2; kt++) {
                unsigned pa0h, pa0l, pa1h, pa1l, pa2h, pa2l, pa3h, pa3l;
                split2t(s[2 * kt][0],     s[2 * kt][1],     pa0h, pa0l);
                split2t(s[2 * kt][2],     s[2 * kt][3],     pa1h, pa1l);
                split2t(s[2 * kt + 1][0], s[2 * kt + 1][1], pa2h, pa2l);
                split2t(s[2 * kt + 1][2], s[2 * kt + 1][3], pa3h, pa3l);
#pragma unroll
                for (int ng = 0; ng < 4; ng++) {
                    const unsigned voff = (unsigned)(
                        (kt * 16 + ((lane >> 3) & 1) * 8 + (lane & 7)) * AT_RS
                        + ng * 16 + (lane >> 4) * 8) * 2;
                    unsigned v0r, v1r, v2r, v3r, w0r, w1r, w2r, w3r;
                    ldmx4t(v0r, v1r, v2r, v3r, kvb + 2 * AKV_ARR * 2 + voff);
                    ldmx4t(w0r, w1r, w2r, w3r, kvb + 3 * AKV_ARR * 2 + voff);
                    mma_bf16(o[2 * ng],     pa0h, pa1h, pa2h, pa3h, v0r, v1r);
                    mma_bf16(o[2 * ng],     pa0h, pa1h, pa2h, pa3h, w0r, w1r);
                    mma_bf16(o[2 * ng],     pa0l, pa1l, pa2l, pa3l, v0r, v1r);
                    mma_bf16(o[2 * ng + 1], pa0h, pa1h, pa2h, pa3h, v2r, v3r);
                    mma_bf16(o[2 * ng + 1], pa0h, pa1h, pa2h, pa3h, w2r, w3r);
                    mma_bf16(o[2 * ng + 1], pa0l, pa1l, pa2l, pa3l, v2r, v3r);
                }
            }
        }

        // ======== half b: softmax (j=4..7) + PV (key groups kt=2,3) ========
        {
            if (diag) {
#pragma unroll
                for (int j = 4; j < 8; j++) {
                    const int cb = kbase + j * 8 + colq;
#pragma unroll
                    for (int e = 0; e < 2; e++) {
                        const int col = cb + e;
                        if (col > r0g) s[j][e]     = -CUDART_INF_F;
                        if (col > r1g) s[j][2 + e] = -CUDART_INF_F;
                    }
                }
            }
#pragma unroll
            for (int j = 4; j < 8; j++) {
                float p0 = fexp2(s[j][0]);
                float p1 = fexp2(s[j][1]);
                float p2 = fexp2(s[j][2]);
                float p3 = fexp2(s[j][3]);
                l0 += p0 + p1; l1 += p2 + p3;
                s[j][0] = p0; s[j][1] = p1; s[j][2] = p2; s[j][3] = p3;
            }
#pragma unroll
            for (int kt = 2; kt < 4; kt++) {
                unsigned pa0h, pa0l, pa1h, pa1l, pa2h, pa2l, pa3h, pa3l;
                split2t(s[2 * kt][0],     s[2 * kt][1],     pa0h, pa0l);
                split2t(s[2 * kt][2],     s[2 * kt][3],     pa1h, pa1l);
                split2t(s[2 * kt + 1][0], s[2 * kt + 1][1], pa2h, pa2l);
                split2t(s[2 * kt + 1][2], s[2 * kt + 1][3], pa3h, pa3l);
#pragma unroll
                for (int ng = 0; ng < 4; ng++) {
                    const unsigned voff = (unsigned)(
                        (kt * 16 + ((lane >> 3) & 1) * 8 + (lane & 7)) * AT_RS
                        + ng * 16 + (lane >> 4) * 8) * 2;
                    unsigned v0r, v1r, v2r, v3r, w0r, w1r, w2r, w3r;
                    ldmx4t(v0r, v1r, v2r, v3r, kvb + 2 * AKV_ARR * 2 + voff);
                    ldmx4t(w0r, w1r, w2r, w3r, kvb + 3 * AKV_ARR * 2 + voff);
                    mma_bf16(o[2 * ng],     pa0h, pa1h, pa2h, pa3h, v0r, v1r);
                    mma_bf16(o[2 * ng],     pa0h, pa1h, pa2h, pa3h, w0r, w1r);
                    mma_bf16(o[2 * ng],     pa0l, pa1l, pa2l, pa3l, v0r, v1r);
                    mma_bf16(o[2 * ng + 1], pa0h, pa1h, pa2h, pa3h, v2r, v3r);
                    mma_bf16(o[2 * ng + 1], pa0h, pa1h, pa2h, pa3h, w2r, w3r);
                    mma_bf16(o[2 * ng + 1], pa0l, pa1l, pa2l, pa3l, v2r, v3r);
                }
            }
        }
        __syncthreads();
    }

    // ---- finalize ----
    l0 += __shfl_xor_sync(0xffffffffu, l0, 1);
    l0 += __shfl_xor_sync(0xffffffffu, l0, 2);
    l1 += __shfl_xor_sync(0xffffffffu, l1, 1);
    l1 += __shfl_xor_sync(0xffffffffu, l1, 2);
    const float inv0 = 1.f / l0;
    const float inv1 = 1.f / l1;

    float* row0 = out + ((size_t)b * TT + r0g) * CC + h * DD;
    float* row1 = out + ((size_t)b * TT + r1g) * CC + h * DD;
#pragma unroll
    for (int j = 0; j < 8; j++) {
        const int c = j * 8 + colq;
        *(float2*)&row0[c] = make_float2(o[j][0] * inv0, o[j][1] * inv0);
        *(float2*)&row1[c] = make_float2(o[j][2] * inv1, o[j][3] * inv1);
    }
}

// ---------------------------------------------------------------------------
extern "C" void kernel_launch(void* const* d_in, const int* in_sizes, int n_in,
                              void* d_out, int out_size)
{
    const float* x    = (const float*)d_in[0];   // [B,T,C]
    const float* w    = (const float*)d_in[1];   // [C, 3C]
    const float* bias = (const float*)d_in[2];   // [3C]
    float* out = (float*)d_out;                  // [B,T,C]

    convert_x_kernel<<<(GM * GK / 4) / 256, 256>>>(x);
    dim3 wgrid(GN / 32, GK / 32);
    convert_w_kernel<<<wgrid, dim3(32, 32)>>>(w);

    cudaFuncSetAttribute(qkv_hmma_kernel,
                         cudaFuncAttributeMaxDynamicSharedMemorySize, GSMEM_B);
    qkv_hmma_kernel<<<GPERS, 128, GSMEM_B>>>(bias);

    const int kAttnSmem = ASM_HALVES * 2;        // 73728 B
    cudaFuncSetAttribute(attn_hmma_kernel,
                         cudaFuncAttributeMaxDynamicSharedMemorySize, kAttnSmem);
    dim3 agrid(TT / 64, BB * HH);                // (32, 64)
    attn_hmma_kernel<<<agrid, 128, kAttnSmem>>>(out);
}